// round 4
// baseline (speedup 1.0000x reference)
#include <cuda_runtime.h>

// out = x @ y  (32x48 @ 48x32 fp32). The W0/W1/W2 one-hot LT matrices plus the
// roll-broadcast / roll-reduce pipeline in the reference compose to exactly
// this matmul (no circular-wrap aliasing); they are never read.
//
// R4: same per-thread work as R3 (15 LDG, 12 FMA, 2 shfl), but 32 CTAs x 128
// threads instead of 128 x 32 — probes whether CTA-distribution overhead is
// part of the ~4.3us fixed floor. Warp w of CTA i computes k-group w of output
// row i; lane = k_local*4 + jseg splits the j-reduction 4 ways per output,
// reduced with a 2-step shfl_xor butterfly. No smem, no block barriers.

#define I_DIM 32
#define J_DIM 48
#define K_DIM 32

__global__ __launch_bounds__(128, 1)
void einsum_matmul_kernel(const float* __restrict__ x,
                          const float* __restrict__ y,
                          float* __restrict__ out) {
    const int i = blockIdx.x;              // output row 0..31
    const int kg = threadIdx.x >> 5;       // k-group 0..3 (warp id)

    const int lane = threadIdx.x & 31;     // 0..31
    const int k_local = lane >> 2;         // 0..7
    const int jseg = lane & 3;             // 0..3
    const int k = kg * 8 + k_local;        // 0..31
    const int j0 = jseg * 12;              // j base for this lane

    // x row slice: 12 floats, 16B-aligned (i*48 and jseg*12 both mult of 4).
    const float4* __restrict__ x4 = (const float4*)(x + i * J_DIM + j0);
    float4 xa = __ldg(&x4[0]);
    float4 xb = __ldg(&x4[1]);
    float4 xc = __ldg(&x4[2]);

    const float* __restrict__ yp = y + j0 * K_DIM + k;

    // 12 independent y loads (front-batched by ptxas), 3 accumulators.
    float y0  = __ldg(&yp[0 * K_DIM]);
    float y1  = __ldg(&yp[1 * K_DIM]);
    float y2  = __ldg(&yp[2 * K_DIM]);
    float y3  = __ldg(&yp[3 * K_DIM]);
    float y4  = __ldg(&yp[4 * K_DIM]);
    float y5  = __ldg(&yp[5 * K_DIM]);
    float y6  = __ldg(&yp[6 * K_DIM]);
    float y7  = __ldg(&yp[7 * K_DIM]);
    float y8  = __ldg(&yp[8 * K_DIM]);
    float y9  = __ldg(&yp[9 * K_DIM]);
    float y10 = __ldg(&yp[10 * K_DIM]);
    float y11 = __ldg(&yp[11 * K_DIM]);

    float a0 = 0.0f, a1 = 0.0f, a2 = 0.0f;
    a0 = fmaf(xa.x, y0, a0);
    a1 = fmaf(xa.y, y1, a1);
    a2 = fmaf(xa.z, y2, a2);
    a0 = fmaf(xa.w, y3, a0);
    a1 = fmaf(xb.x, y4, a1);
    a2 = fmaf(xb.y, y5, a2);
    a0 = fmaf(xb.z, y6, a0);
    a1 = fmaf(xb.w, y7, a1);
    a2 = fmaf(xc.x, y8, a2);
    a0 = fmaf(xc.y, y9, a0);
    a1 = fmaf(xc.z, y10, a1);
    a2 = fmaf(xc.w, y11, a2);

    float acc = (a0 + a1) + a2;

    // Butterfly reduce over the 4 jseg lanes (consecutive lanes).
    acc += __shfl_xor_sync(0xFFFFFFFFu, acc, 1);
    acc += __shfl_xor_sync(0xFFFFFFFFu, acc, 2);

    if (jseg == 0) {
        out[i * K_DIM + k] = acc;   // 32 contiguous floats per CTA
    }
}

extern "C" void kernel_launch(void* const* d_in, const int* in_sizes, int n_in,
                              void* d_out, int out_size) {
    const float* x = (const float*)d_in[0];
    const float* y = (const float*)d_in[1];
    float* out = (float*)d_out;
    einsum_matmul_kernel<<<I_DIM, 128>>>(x, y, out);
}

// round 5
// speedup vs baseline: 1.2313x; 1.2313x over previous
#include <cuda_runtime.h>

// out = x @ y  (32x48 @ 48x32 fp32). The W0/W1/W2 one-hot LT matrices plus the
// roll-broadcast / roll-reduce pipeline in the reference compose to exactly
// this matmul (no circular-wrap aliasing); they are never read.
//
// R5: revert to R3's best-measured config (128 CTAs x 32 threads; bench 5.088,
// kernel 4.32us). Kernel-level dur has been flat ~4.2-4.6us across radically
// different structures -> fixed launch/ramp floor; bench deltas <0.5us are
// noise. Micro-trims only: store address computed before the shuffle tail.
//
// Layout: blockIdx b -> i = b>>2 (row), kg = b&3 (8-k group).
// lane = k_local*4 + jseg: lane sums j in [jseg*12, jseg*12+12).
// Per thread: 3 float4 x-loads + 12 y-loads + 12 FMA, 2-step shfl_xor
// butterfly over jseg lanes, lane with jseg==0 stores. No smem, no barriers.

#define I_DIM 32
#define J_DIM 48
#define K_DIM 32

__global__ __launch_bounds__(32, 1)
void einsum_matmul_kernel(const float* __restrict__ x,
                          const float* __restrict__ y,
                          float* __restrict__ out) {
    const int b = blockIdx.x;          // 0..127
    const int i = b >> 2;              // output row 0..31
    const int kg = b & 3;              // k-group 0..3

    const int lane = threadIdx.x;      // 0..31
    const int k_local = lane >> 2;     // 0..7
    const int jseg = lane & 3;         // 0..3
    const int k = kg * 8 + k_local;    // 0..31
    const int j0 = jseg * 12;          // j base for this lane

    // Store address ready early (off the post-shuffle critical path).
    float* __restrict__ op = out + i * K_DIM + k;

    // x row slice: 12 floats, 16B-aligned (i*48 and jseg*12 both mult of 4).
    const float4* __restrict__ x4 = (const float4*)(x + i * J_DIM + j0);
    float4 xa = __ldg(&x4[0]);
    float4 xb = __ldg(&x4[1]);
    float4 xc = __ldg(&x4[2]);

    const float* __restrict__ yp = y + j0 * K_DIM + k;

    // 12 independent y loads (front-batched by ptxas), 3 accumulators.
    float y0  = __ldg(&yp[0 * K_DIM]);
    float y1  = __ldg(&yp[1 * K_DIM]);
    float y2  = __ldg(&yp[2 * K_DIM]);
    float y3  = __ldg(&yp[3 * K_DIM]);
    float y4  = __ldg(&yp[4 * K_DIM]);
    float y5  = __ldg(&yp[5 * K_DIM]);
    float y6  = __ldg(&yp[6 * K_DIM]);
    float y7  = __ldg(&yp[7 * K_DIM]);
    float y8  = __ldg(&yp[8 * K_DIM]);
    float y9  = __ldg(&yp[9 * K_DIM]);
    float y10 = __ldg(&yp[10 * K_DIM]);
    float y11 = __ldg(&yp[11 * K_DIM]);

    float a0 = 0.0f, a1 = 0.0f, a2 = 0.0f;
    a0 = fmaf(xa.x, y0, a0);
    a1 = fmaf(xa.y, y1, a1);
    a2 = fmaf(xa.z, y2, a2);
    a0 = fmaf(xa.w, y3, a0);
    a1 = fmaf(xb.x, y4, a1);
    a2 = fmaf(xb.y, y5, a2);
    a0 = fmaf(xb.z, y6, a0);
    a1 = fmaf(xb.w, y7, a1);
    a2 = fmaf(xc.x, y8, a2);
    a0 = fmaf(xc.y, y9, a0);
    a1 = fmaf(xc.z, y10, a1);
    a2 = fmaf(xc.w, y11, a2);

    float acc = (a0 + a1) + a2;

    // Butterfly reduce over the 4 jseg lanes (consecutive lanes).
    acc += __shfl_xor_sync(0xFFFFFFFFu, acc, 1);
    acc += __shfl_xor_sync(0xFFFFFFFFu, acc, 2);

    if (jseg == 0) {
        *op = acc;
    }
}

extern "C" void kernel_launch(void* const* d_in, const int* in_sizes, int n_in,
                              void* d_out, int out_size) {
    const float* x = (const float*)d_in[0];
    const float* y = (const float*)d_in[1];
    float* out = (float*)d_out;
    einsum_matmul_kernel<<<128, 32>>>(x, y, out);
}